// round 4
// baseline (speedup 1.0000x reference)
#include <cuda_runtime.h>
#include <math.h>

#define H 256
#define N_STATE 64
#define L 2048
#define BATCH 8

#define OT 512          // output tile (time) per block
#define MT 512          // input tile (time)
#define NTHREADS 64     // each thread owns 8 consecutive lags x 2 batches
#define KTOT 1032       // k values per tile (q range)
#define KSM_SZ 1168     // skewed storage: max a(i)=1031+128=1159, padded

typedef unsigned long long ull;

// scratch (no allocation allowed)
__device__ float4 g_params[H * N_STATE];   // {Ceff_r, Ceff_i, dtA_r, dtA_i}
__device__ float  g_k[H * L];              // SSM convolution kernel
__device__ int    g_lcut[H];               // per-head kernel cutoff

#define FMA2(acc, a, b) asm("fma.rn.f32x2 %0, %1, %2, %0;" : "+l"(acc) : "l"(a), "l"(b))
#define DUP2(dst, src) asm("mov.b64 %0, {%1, %1};" : "=l"(dst) : "r"(src))

// ---------------------------------------------------------------------------
// Kernel 1: per-(h,n) parameters, replicating the reference's fp32 op order.
// ---------------------------------------------------------------------------
__global__ void s4d_params_kernel(const float* __restrict__ A_real,
                                  const float* __restrict__ A_imag,
                                  const float* __restrict__ Bm,
                                  const float* __restrict__ Cm,
                                  const float* __restrict__ inv_dt)
{
    int idx = blockIdx.x * blockDim.x + threadIdx.x;
    if (idx >= H * N_STATE) return;
    int h = idx / N_STATE;

    float Ar = -expf(A_real[idx]);          // A = -exp(A_real) - i*A_imag
    float Ai = -A_imag[idx];
    float dt = (float)exp((double)inv_dt[h]);
    float dtAr = dt * Ar;
    float dtAi = dt * Ai;

    float er = expf(dtAr);
    double sd, cd;
    sincos((double)dtAi, &sd, &cd);
    float Er = fmaf(er, (float)cd, -1.0f);
    float Ei = er * (float)sd;

    float br = Bm[2 * idx], bi = Bm[2 * idx + 1];
    float cr = Cm[2 * idx], ci = Cm[2 * idx + 1];
    float bcr = br * cr - bi * ci;
    float bci = br * ci + bi * cr;
    float tr = bcr * Er - bci * Ei;
    float ti = bcr * Ei + bci * Er;
    float inv = 1.0f / (Ar * Ar + Ai * Ai);
    float cer = (tr * Ar + ti * Ai) * inv;
    float cei = (ti * Ar - tr * Ai) * inv;

    g_params[idx] = make_float4(cer, cei, dtAr, dtAi);

    // per-head truncation point: decay e^{dtAr*l}; cut at e^-16 (~1.1e-7)
    if ((idx & (N_STATE - 1)) == 0) {
        float rate = -dtAr;                 // > 0
        int lc = (int)(16.0f / rate) + 1;
        g_lcut[h] = lc < L ? lc : L;
    }
}

// ---------------------------------------------------------------------------
// Kernel 2: k[h,l] = 2 * sum_n Re(Ceff * exp(dtA_r*l) * cis(fl32(dtA_i*l)))
// ---------------------------------------------------------------------------
__global__ void s4d_kgen_kernel(void)
{
    __shared__ float4 sp[N_STATE];
    int h = blockIdx.y;
    int l = blockIdx.x * blockDim.x + threadIdx.x;
    if (threadIdx.x < N_STATE) sp[threadIdx.x] = g_params[h * N_STATE + threadIdx.x];
    __syncthreads();

    const double INV2PI = 0.15915494309189535;
    const double TWOPI  = 6.283185307179586;
    const float  TWO_OVER_PI = 0.6366197723675814f;
    const float  PIO2_HI = 1.57079637050628662109375f;
    const float  PIO2_LO = -4.37113900018624283e-8f;

    float fl = (float)l;
    float acc = 0.0f;

    #pragma unroll 4
    for (int n = 0; n < N_STATE; n++) {
        float4 p = sp[n];
        float theta = p.w * fl;                 // fp32 product — matches reference
        float decay = expf(p.z * fl);

        double td = (double)theta;
        double qd = rint(td * INV2PI);
        float r = (float)fma(-qd, TWOPI, td);

        float qf = rintf(r * TWO_OVER_PI);
        float rr = fmaf(-qf, PIO2_HI, r);
        rr = fmaf(-qf, PIO2_LO, rr);
        int qi = (int)qf & 3;

        float x2 = rr * rr;
        float s = fmaf(x2, 2.75573192e-6f, -1.98412698e-4f);
        s = fmaf(x2, s, 8.33333333e-3f);
        s = fmaf(x2, s, -1.66666667e-1f);
        s = rr * fmaf(x2, s, 1.0f);
        float c = fmaf(x2, 2.48015873e-5f, -1.38888889e-3f);
        c = fmaf(x2, c, 4.16666667e-2f);
        c = fmaf(x2, c, -0.5f);
        c = fmaf(x2, c, 1.0f);

        float S, C;
        switch (qi) {
            case 0: S = s;  C = c;  break;
            case 1: S = c;  C = -s; break;
            case 2: S = -s; C = -c; break;
            default: S = -c; C = s; break;
        }
        acc = fmaf(decay, fmaf(p.x, C, -p.y * S), acc);
    }
    g_k[h * L + l] = 2.0f * acc;
}

// ---------------------------------------------------------------------------
// Kernel 3: causal conv for a BATCH PAIR with packed fma.rn.f32x2.
// Same skeleton as R3 (proven conflict-free): k scalar in SKEWED smem
// (a(i)=i+(i>>3)), 16-entry circular k window, but the window registers hold
// DUPLICATED (k,k) 64-bit pairs (dup happens in-register on the ALU pipe) and
// each accumulator holds (y_b0, y_b1). x pairs interleaved in smem; reads are
// 16B broadcasts. Arithmetic is bitwise identical to the scalar version.
// ---------------------------------------------------------------------------
__global__ void __launch_bounds__(NTHREADS)
s4d_conv_kernel(const float* __restrict__ x, float* __restrict__ y)
{
    __shared__ __align__(16) float2 xs2[MT];
    __shared__ __align__(16) float  ksm[KSM_SZ];

    int t0 = blockIdx.x * OT;
    int h  = blockIdx.y;
    int b0 = blockIdx.z * 2;
    int tid = threadIdx.x;

    const float* xrow0 = x + (b0 * H + h) * L;
    const float* xrow1 = x + ((b0 + 1) * H + h) * L;
    const float* krow  = g_k + h * L;
    int lcut = g_lcut[h];

    ull acc[8];
    #pragma unroll
    for (int j = 0; j < 8; j++) acc[j] = 0ull;

    int ms = t0 - lcut;
    int m0_start = ms > 0 ? (ms / MT) * MT : 0;
    int s_bt = 8 * tid + MT + 7;     // sidx of this thread's q = b_t (j=0 lag base)

    for (int m0 = m0_start; m0 <= t0; m0 += MT) {
        int qlo = t0 - m0 - MT - 7;  // q stored at sidx = q - qlo
        __syncthreads();
        #pragma unroll
        for (int i = tid; i < MT; i += NTHREADS)
            xs2[i] = make_float2(xrow0[m0 + i], xrow1[m0 + i]);
        #pragma unroll
        for (int i = tid; i < KTOT; i += NTHREADS) {
            int q = qlo + i;
            ksm[i + (i >> 3)] = (q >= 0 && q < L) ? krow[q] : 0.0f;
        }
        __syncthreads();

        // init 16-entry circular window of duplicated (k,k) pairs
        ull kw[16];
        #pragma unroll
        for (int v = -8; v <= 7; v++) {
            int sidx = s_bt - v;
            DUP2(kw[v & 15], __float_as_uint(ksm[sidx + (sidx >> 3)]));
        }
        int sidx0 = s_bt - 8;                 // == 7 (mod 8) by construction
        int ab = sidx0 + (sidx0 >> 3);        // skewed addr; -18 per macro-block

        #pragma unroll 1
        for (int mb = 0; mb < MT / 16; mb++) {
            #pragma unroll
            for (int up = 0; up < 8; up++) {
                // one 16B broadcast load covers two m-steps' (b0,b1) pairs
                ulonglong2 xv = *(const ulonglong2*)&xs2[16 * mb + 2 * up];
                {
                    const int u = 2 * up;
                    #pragma unroll
                    for (int j = 0; j < 8; j++)
                        FMA2(acc[j], kw[(u - j) & 15], xv.x);
                    DUP2(kw[(u + 8) & 15],
                         __float_as_uint(ksm[ab - u - (u >= 8 ? 1 : 0)]));
                }
                {
                    const int u = 2 * up + 1;
                    #pragma unroll
                    for (int j = 0; j < 8; j++)
                        FMA2(acc[j], kw[(u - j) & 15], xv.y);
                    DUP2(kw[(u + 8) & 15],
                         __float_as_uint(ksm[ab - u - (u >= 8 ? 1 : 0)]));
                }
            }
            ab -= 18;
        }
    }

    // epilogue: unpack, ReLU, vectorized stores
    float r0[8], r1[8];
    #pragma unroll
    for (int j = 0; j < 8; j++) {
        float v0 = __uint_as_float((unsigned int)(acc[j] & 0xffffffffull));
        float v1 = __uint_as_float((unsigned int)(acc[j] >> 32));
        r0[j] = v0 > 0.0f ? v0 : 0.0f;
        r1[j] = v1 > 0.0f ? v1 : 0.0f;
    }
    float* yr0 = y + (b0 * H + h) * L + t0 + 8 * tid;
    float* yr1 = y + ((b0 + 1) * H + h) * L + t0 + 8 * tid;
    *(float4*)(yr0)     = make_float4(r0[0], r0[1], r0[2], r0[3]);
    *(float4*)(yr0 + 4) = make_float4(r0[4], r0[5], r0[6], r0[7]);
    *(float4*)(yr1)     = make_float4(r1[0], r1[1], r1[2], r1[3]);
    *(float4*)(yr1 + 4) = make_float4(r1[4], r1[5], r1[6], r1[7]);
}

// ---------------------------------------------------------------------------
extern "C" void kernel_launch(void* const* d_in, const int* in_sizes, int n_in,
                              void* d_out, int out_size)
{
    const float* x      = (const float*)d_in[0];   // (B, H, L)
    const float* A_real = (const float*)d_in[1];   // (H, N)
    const float* A_imag = (const float*)d_in[2];   // (H, N)
    const float* Bm     = (const float*)d_in[3];   // (1, H, N, 2)
    const float* Cm     = (const float*)d_in[4];   // (1, H, N, 2)
    const float* inv_dt = (const float*)d_in[5];   // (H, 1)
    float* y = (float*)d_out;                      // (B, 1, H, L)

    s4d_params_kernel<<<(H * N_STATE + 255) / 256, 256>>>(A_real, A_imag, Bm, Cm, inv_dt);
    s4d_kgen_kernel<<<dim3(L / 256, H), 256>>>();
    s4d_conv_kernel<<<dim3(L / OT, H, BATCH / 2), NTHREADS>>>(x, y);
}

// round 5
// speedup vs baseline: 1.9963x; 1.9963x over previous
#include <cuda_runtime.h>
#include <math.h>

#define H 256
#define N_STATE 64
#define L 2048
#define BATCH 8

#define OT 512          // output tile (time) per block
#define MT 512          // input tile (time)
#define NTHREADS 64     // each thread owns 8 consecutive outputs
#define KTOT 1032       // k values per tile (q range)
#define KSM_SZ 1168     // skewed storage: max a(i)=1031+128=1159, padded

// scratch (no allocation allowed)
__device__ float g_k[H * L];               // SSM convolution kernel

// ---------------------------------------------------------------------------
// FP32-only accurate sin/cos for |theta| <= ~4.1e4.
// 3-term Cody-Waite 2*pi reduction: q <= 6446 < 2^13; T1,T2 have <=11 mantissa
// bits so q*T1, q*T2 are exact. Residual phase error ~1e-8 rad.
// ---------------------------------------------------------------------------
__device__ __forceinline__ void sincos_cw(float theta, float& S, float& C)
{
    const float INV2PI = 0.15915494309189535f;
    const float T1 = 6.28125f;                     // 8-bit exact chunk of 2pi
    const float T2 = 1.93500518798828125e-3f;      // 11-bit exact chunk
    const float T3 = 3.01991598e-7f;               // fp32 tail
    const float TWO_OVER_PI = 0.6366197723675814f;
    const float PIO2_HI = 1.57079637050628662109375f;
    const float PIO2_LO = -4.37113900018624283e-8f;

    float q = rintf(theta * INV2PI);
    float r = fmaf(-q, T1, theta);
    r = fmaf(-q, T2, r);
    r = fmaf(-q, T3, r);                           // r in [-pi, pi]

    float qf = rintf(r * TWO_OVER_PI);
    float rr = fmaf(-qf, PIO2_HI, r);
    rr = fmaf(-qf, PIO2_LO, rr);
    int qi = (int)qf & 3;

    float x2 = rr * rr;
    float s = fmaf(x2, 2.75573192e-6f, -1.98412698e-4f);
    s = fmaf(x2, s, 8.33333333e-3f);
    s = fmaf(x2, s, -1.66666667e-1f);
    s = rr * fmaf(x2, s, 1.0f);
    float c = fmaf(x2, 2.48015873e-5f, -1.38888889e-3f);
    c = fmaf(x2, c, 4.16666667e-2f);
    c = fmaf(x2, c, -0.5f);
    c = fmaf(x2, c, 1.0f);

    switch (qi) {
        case 0: S = s;  C = c;  break;
        case 1: S = c;  C = -s; break;
        case 2: S = -s; C = -c; break;
        default: S = -c; C = s; break;
    }
}

// ---------------------------------------------------------------------------
// Kernel 1 (fused params + kgen): per head h, compute the 64 complex poles in
// smem (threads 0..63), then k[h,l] = 2*sum_n Re(Ceff * exp(dtA_r*l) *
// cis(fl32(dtA_i*l))) for 256 l's per block. No FP64 in the hot loop; one
// double exp per block to match XLA's fp32 exp(inv_dt) rounding exactly.
// ---------------------------------------------------------------------------
__global__ void s4d_kgen_kernel(const float* __restrict__ A_real,
                                const float* __restrict__ A_imag,
                                const float* __restrict__ Bm,
                                const float* __restrict__ Cm,
                                const float* __restrict__ inv_dt)
{
    __shared__ float4 sp[N_STATE];
    __shared__ float sdt;
    int h = blockIdx.y;
    int tid = threadIdx.x;

    if (tid == 0) sdt = (float)exp((double)inv_dt[h]);
    __syncthreads();

    if (tid < N_STATE) {
        int idx = h * N_STATE + tid;
        float Ar = -expf(A_real[idx]);      // A = -exp(A_real) - i*A_imag
        float Ai = -A_imag[idx];
        float dt = sdt;
        float dtAr = dt * Ar;
        float dtAi = dt * Ai;

        float er = expf(dtAr);
        float S, C;
        sincos_cw(dtAi, S, C);              // |dtAi| <= ~20
        float Er = fmaf(er, C, -1.0f);      // exp(dtA) - 1
        float Ei = er * S;

        float br = Bm[2 * idx], bi = Bm[2 * idx + 1];
        float cr = Cm[2 * idx], ci = Cm[2 * idx + 1];
        float bcr = br * cr - bi * ci;
        float bci = br * ci + bi * cr;
        float tr = bcr * Er - bci * Ei;
        float ti = bcr * Ei + bci * Er;
        float inv = 1.0f / (Ar * Ar + Ai * Ai);
        float cer = (tr * Ar + ti * Ai) * inv;
        float cei = (ti * Ar - tr * Ai) * inv;
        sp[tid] = make_float4(cer, cei, dtAr, dtAi);
    }
    __syncthreads();

    int l = blockIdx.x * blockDim.x + tid;
    float fl = (float)l;
    float acc = 0.0f;

    #pragma unroll 4
    for (int n = 0; n < N_STATE; n++) {
        float4 p = sp[n];
        float theta = p.w * fl;             // fp32 product — matches reference
        float decay = expf(p.z * fl);
        float S, C;
        sincos_cw(theta, S, C);
        acc = fmaf(decay, fmaf(p.x, C, -p.y * S), acc);
    }
    g_k[h * L + l] = 2.0f * acc;
}

// ---------------------------------------------------------------------------
// Kernel 2: causal conv y[b,h,l] = sum_{m<=l} k[l-m]*x[m], then ReLU.
// (R3 structure: skewed conflict-free smem k, 16-register circular window.)
// ---------------------------------------------------------------------------
__global__ void __launch_bounds__(NTHREADS)
s4d_conv_kernel(const float* __restrict__ x, float* __restrict__ y,
                const float* __restrict__ A_real,
                const float* __restrict__ inv_dt)
{
    __shared__ __align__(16) float xs[MT];
    __shared__ __align__(16) float ksm[KSM_SZ];

    int t0 = blockIdx.x * OT;
    int h  = blockIdx.y;
    int b  = blockIdx.z;
    int tid = threadIdx.x;

    const float* xrow = x + (b * H + h) * L;
    const float* krow = g_k + h * L;

    // per-head truncation: decay rate = dt*exp(A_real); cut at e^-16 (~1.1e-7)
    float rate = expf(inv_dt[h]) * expf(A_real[h * N_STATE]);
    int lcut = (int)(16.0f / rate) + 1;
    if (lcut > L) lcut = L;

    float acc[8];
    #pragma unroll
    for (int j = 0; j < 8; j++) acc[j] = 0.0f;

    int ms = t0 - lcut;
    int m0_start = ms > 0 ? (ms / MT) * MT : 0;
    int s_bt = 8 * tid + MT + 7;     // sidx of this thread's q = b_t (j=0 lag base)

    for (int m0 = m0_start; m0 <= t0; m0 += MT) {
        int qlo = t0 - m0 - MT - 7;  // q stored at sidx = q - qlo
        __syncthreads();
        #pragma unroll
        for (int i = tid; i < MT; i += NTHREADS) xs[i] = xrow[m0 + i];
        #pragma unroll
        for (int i = tid; i < KTOT; i += NTHREADS) {
            int q = qlo + i;
            ksm[i + (i >> 3)] = (q >= 0 && q < L) ? krow[q] : 0.0f;
        }
        __syncthreads();

        // init 16-entry circular k window: entry (v&15) holds k at lag b_t - v
        float kw[16];
        #pragma unroll
        for (int v = -8; v <= 7; v++) {
            int sidx = s_bt - v;
            kw[v & 15] = ksm[sidx + (sidx >> 3)];
        }
        int sidx0 = s_bt - 8;                 // == 7 (mod 8) by construction
        int ab = sidx0 + (sidx0 >> 3);        // skewed addr; -18 per macro-block

        #pragma unroll 1
        for (int mb = 0; mb < MT / 16; mb++) {
            float xr[16];
            #pragma unroll
            for (int g = 0; g < 4; g++) {
                float4 xv = *(const float4*)&xs[16 * mb + 4 * g];
                xr[4 * g + 0] = xv.x; xr[4 * g + 1] = xv.y;
                xr[4 * g + 2] = xv.z; xr[4 * g + 3] = xv.w;
            }
            #pragma unroll
            for (int u = 0; u < 16; u++) {
                float xu = xr[u];
                #pragma unroll
                for (int j = 0; j < 8; j++)
                    acc[j] = fmaf(kw[(u - j) & 15], xu, acc[j]);
                // refill: load lag value for 8 steps ahead
                kw[(u + 8) & 15] = ksm[ab - u - (u >= 8 ? 1 : 0)];
            }
            ab -= 18;
        }
    }

    float* yrow = y + (b * H + h) * L + t0 + 8 * tid;
    float r[8];
    #pragma unroll
    for (int j = 0; j < 8; j++) r[j] = acc[j] > 0.0f ? acc[j] : 0.0f;
    *(float4*)(yrow)     = make_float4(r[0], r[1], r[2], r[3]);
    *(float4*)(yrow + 4) = make_float4(r[4], r[5], r[6], r[7]);
}

// ---------------------------------------------------------------------------
extern "C" void kernel_launch(void* const* d_in, const int* in_sizes, int n_in,
                              void* d_out, int out_size)
{
    const float* x      = (const float*)d_in[0];   // (B, H, L)
    const float* A_real = (const float*)d_in[1];   // (H, N)
    const float* A_imag = (const float*)d_in[2];   // (H, N)
    const float* Bm     = (const float*)d_in[3];   // (1, H, N, 2)
    const float* Cm     = (const float*)d_in[4];   // (1, H, N, 2)
    const float* inv_dt = (const float*)d_in[5];   // (H, 1)
    float* y = (float*)d_out;                      // (B, 1, H, L)

    s4d_kgen_kernel<<<dim3(L / 256, H), 256>>>(A_real, A_imag, Bm, Cm, inv_dt);
    s4d_conv_kernel<<<dim3(L / OT, H, BATCH), NTHREADS>>>(x, y, A_real, inv_dt);
}

// round 6
// speedup vs baseline: 2.0925x; 1.0482x over previous
#include <cuda_runtime.h>
#include <math.h>

#define H 256
#define N_STATE 64
#define L 2048
#define BATCH 8

#define OT 512          // output tile (time) per block
#define MT 512          // input tile (time)
#define NTHREADS 64     // each thread owns 8 consecutive lags x 2 batches
#define KTOT 1032       // k values per tile (q range)
#define KSM_SZ 1168     // skewed storage: max a(i)=1031+128=1159, padded

typedef unsigned long long ull;

// scratch (no allocation allowed)
__device__ float g_k[H * L];               // SSM convolution kernel

#define FMA2(acc, a, b) asm("fma.rn.f32x2 %0, %1, %2, %0;" : "+l"(acc) : "l"(a), "l"(b))

// ---------------------------------------------------------------------------
// FP32-only accurate sin/cos for |theta| <= ~4.1e4 (3-term Cody-Waite).
// ---------------------------------------------------------------------------
__device__ __forceinline__ void sincos_cw(float theta, float& S, float& C)
{
    const float INV2PI = 0.15915494309189535f;
    const float T1 = 6.28125f;
    const float T2 = 1.93500518798828125e-3f;
    const float T3 = 3.01991598e-7f;
    const float TWO_OVER_PI = 0.6366197723675814f;
    const float PIO2_HI = 1.57079637050628662109375f;
    const float PIO2_LO = -4.37113900018624283e-8f;

    float q = rintf(theta * INV2PI);
    float r = fmaf(-q, T1, theta);
    r = fmaf(-q, T2, r);
    r = fmaf(-q, T3, r);

    float qf = rintf(r * TWO_OVER_PI);
    float rr = fmaf(-qf, PIO2_HI, r);
    rr = fmaf(-qf, PIO2_LO, rr);
    int qi = (int)qf & 3;

    float x2 = rr * rr;
    float s = fmaf(x2, 2.75573192e-6f, -1.98412698e-4f);
    s = fmaf(x2, s, 8.33333333e-3f);
    s = fmaf(x2, s, -1.66666667e-1f);
    s = rr * fmaf(x2, s, 1.0f);
    float c = fmaf(x2, 2.48015873e-5f, -1.38888889e-3f);
    c = fmaf(x2, c, 4.16666667e-2f);
    c = fmaf(x2, c, -0.5f);
    c = fmaf(x2, c, 1.0f);

    switch (qi) {
        case 0: S = s;  C = c;  break;
        case 1: S = c;  C = -s; break;
        case 2: S = -s; C = -c; break;
        default: S = -c; C = s; break;
    }
}

// ---------------------------------------------------------------------------
// Kernel 1 (fused params + kgen): no FP64 in the hot loop.
// ---------------------------------------------------------------------------
__global__ void s4d_kgen_kernel(const float* __restrict__ A_real,
                                const float* __restrict__ A_imag,
                                const float* __restrict__ Bm,
                                const float* __restrict__ Cm,
                                const float* __restrict__ inv_dt)
{
    __shared__ float4 sp[N_STATE];
    __shared__ float sdt;
    int h = blockIdx.y;
    int tid = threadIdx.x;

    if (tid == 0) sdt = (float)exp((double)inv_dt[h]);
    __syncthreads();

    if (tid < N_STATE) {
        int idx = h * N_STATE + tid;
        float Ar = -expf(A_real[idx]);      // A = -exp(A_real) - i*A_imag
        float Ai = -A_imag[idx];
        float dt = sdt;
        float dtAr = dt * Ar;
        float dtAi = dt * Ai;

        float er = expf(dtAr);
        float S, C;
        sincos_cw(dtAi, S, C);
        float Er = fmaf(er, C, -1.0f);
        float Ei = er * S;

        float br = Bm[2 * idx], bi = Bm[2 * idx + 1];
        float cr = Cm[2 * idx], ci = Cm[2 * idx + 1];
        float bcr = br * cr - bi * ci;
        float bci = br * ci + bi * cr;
        float tr = bcr * Er - bci * Ei;
        float ti = bcr * Ei + bci * Er;
        float inv = 1.0f / (Ar * Ar + Ai * Ai);
        float cer = (tr * Ar + ti * Ai) * inv;
        float cei = (ti * Ar - tr * Ai) * inv;
        sp[tid] = make_float4(cer, cei, dtAr, dtAi);
    }
    __syncthreads();

    int l = blockIdx.x * blockDim.x + tid;
    float fl = (float)l;
    float acc = 0.0f;

    #pragma unroll 4
    for (int n = 0; n < N_STATE; n++) {
        float4 p = sp[n];
        float theta = p.w * fl;             // fp32 product — matches reference
        float decay = expf(p.z * fl);
        float S, C;
        sincos_cw(theta, S, C);
        acc = fmaf(decay, fmaf(p.x, C, -p.y * S), acc);
    }
    g_k[h * L + l] = 2.0f * acc;
}

// ---------------------------------------------------------------------------
// Kernel 2: causal conv for a BATCH PAIR with packed fma.rn.f32x2.
// R3's proven skeleton, ull flavor: k stored PRE-DUPLICATED (k,k) in skewed
// smem (a(i)=i+(i>>3), 2-way = the 64-bit LDS floor); 16-entry circular
// window of ull; zero packing instructions in the inner loop. x pairs
// interleaved; one 16B broadcast covers two m-steps.
// ---------------------------------------------------------------------------
__global__ void __launch_bounds__(NTHREADS)
s4d_conv_kernel(const float* __restrict__ x, float* __restrict__ y,
                const float* __restrict__ A_real,
                const float* __restrict__ inv_dt)
{
    __shared__ __align__(16) float2 xs2[MT];
    __shared__ __align__(16) ull   kdup[KSM_SZ];

    int t0 = blockIdx.x * OT;
    int h  = blockIdx.y;
    int b0 = blockIdx.z * 2;
    int tid = threadIdx.x;

    const float* xrow0 = x + (b0 * H + h) * L;
    const float* xrow1 = x + ((b0 + 1) * H + h) * L;
    const float* krow  = g_k + h * L;

    // per-head truncation: decay rate = dt*exp(A_real); cut at e^-9 (~1.2e-4)
    float rate = expf(inv_dt[h]) * expf(A_real[h * N_STATE]);
    int lcut = (int)(9.0f / rate) + 1;
    if (lcut > L) lcut = L;

    ull acc[8];
    #pragma unroll
    for (int j = 0; j < 8; j++) acc[j] = 0ull;

    int ms = t0 - lcut;
    int m0_start = ms > 0 ? (ms / MT) * MT : 0;
    int s_bt = 8 * tid + MT + 7;     // sidx of this thread's q = b_t (j=0 lag base)

    for (int m0 = m0_start; m0 <= t0; m0 += MT) {
        int qlo = t0 - m0 - MT - 7;  // q stored at sidx = q - qlo
        __syncthreads();
        #pragma unroll
        for (int i = tid; i < MT; i += NTHREADS)
            xs2[i] = make_float2(xrow0[m0 + i], xrow1[m0 + i]);
        #pragma unroll
        for (int i = tid; i < KTOT; i += NTHREADS) {
            int q = qlo + i;
            float kv = (q >= 0 && q < L) ? krow[q] : 0.0f;
            unsigned int u = __float_as_uint(kv);
            kdup[i + (i >> 3)] = ((ull)u << 32) | u;
        }
        __syncthreads();

        // init 16-entry circular window: entry (v&15) holds (k,k) at lag b_t - v
        ull kw[16];
        #pragma unroll
        for (int v = -8; v <= 7; v++) {
            int sidx = s_bt - v;
            kw[v & 15] = kdup[sidx + (sidx >> 3)];
        }
        int sidx0 = s_bt - 8;                 // == 7 (mod 8) by construction
        int ab = sidx0 + (sidx0 >> 3);        // skewed addr; -18 per macro-block

        #pragma unroll 1
        for (int mb = 0; mb < MT / 16; mb++) {
            #pragma unroll
            for (int up = 0; up < 8; up++) {
                // one 16B broadcast covers two m-steps' (b0,b1) pairs
                ulonglong2 xv = *(const ulonglong2*)&xs2[16 * mb + 2 * up];
                {
                    const int u = 2 * up;
                    #pragma unroll
                    for (int j = 0; j < 8; j++)
                        FMA2(acc[j], kw[(u - j) & 15], xv.x);
                    kw[(u + 8) & 15] = kdup[ab - u - (u >= 8 ? 1 : 0)];
                }
                {
                    const int u = 2 * up + 1;
                    #pragma unroll
                    for (int j = 0; j < 8; j++)
                        FMA2(acc[j], kw[(u - j) & 15], xv.y);
                    kw[(u + 8) & 15] = kdup[ab - u - (u >= 8 ? 1 : 0)];
                }
            }
            ab -= 18;
        }
    }

    // epilogue: unpack, ReLU, vectorized stores
    float r0[8], r1[8];
    #pragma unroll
    for (int j = 0; j < 8; j++) {
        float v0 = __uint_as_float((unsigned int)(acc[j] & 0xffffffffull));
        float v1 = __uint_as_float((unsigned int)(acc[j] >> 32));
        r0[j] = v0 > 0.0f ? v0 : 0.0f;
        r1[j] = v1 > 0.0f ? v1 : 0.0f;
    }
    float* yr0 = y + (b0 * H + h) * L + t0 + 8 * tid;
    float* yr1 = y + ((b0 + 1) * H + h) * L + t0 + 8 * tid;
    *(float4*)(yr0)     = make_float4(r0[0], r0[1], r0[2], r0[3]);
    *(float4*)(yr0 + 4) = make_float4(r0[4], r0[5], r0[6], r0[7]);
    *(float4*)(yr1)     = make_float4(r1[0], r1[1], r1[2], r1[3]);
    *(float4*)(yr1 + 4) = make_float4(r1[4], r1[5], r1[6], r1[7]);
}

// ---------------------------------------------------------------------------
extern "C" void kernel_launch(void* const* d_in, const int* in_sizes, int n_in,
                              void* d_out, int out_size)
{
    const float* x      = (const float*)d_in[0];   // (B, H, L)
    const float* A_real = (const float*)d_in[1];   // (H, N)
    const float* A_imag = (const float*)d_in[2];   // (H, N)
    const float* Bm     = (const float*)d_in[3];   // (1, H, N, 2)
    const float* Cm     = (const float*)d_in[4];   // (1, H, N, 2)
    const float* inv_dt = (const float*)d_in[5];   // (H, 1)
    float* y = (float*)d_out;                      // (B, 1, H, L)

    s4d_kgen_kernel<<<dim3(L / 256, H), 256>>>(A_real, A_imag, Bm, Cm, inv_dt);
    s4d_conv_kernel<<<dim3(L / OT, H, BATCH / 2), NTHREADS>>>(x, y, A_real, inv_dt);
}

// round 8
// speedup vs baseline: 2.4273x; 1.1600x over previous
#include <cuda_runtime.h>
#include <cuda_bf16.h>
#include <math.h>
#include <stdint.h>

#define H 256
#define N_STATE 64
#define L 2048
#define BATCH 8
#define THREADS 256
#define KPAD 16

// ---- dynamic smem layout (byte offsets from 128-aligned base) ----
#define OFF_XHI   0              // u32[1024*8]: (xhi[2j],xhi[2j+1]) per batch col
#define OFF_XLO   32768
#define OFF_KARR  65536          // u32[2064]: (khi | klo<<16), [0,16) zero pad
#define OFF_AHI   73856          // 16x16 bf16 Toeplitz tile (512B)
#define OFF_ALO   74368
#define SMEM_DYN  75008

__device__ __forceinline__ uint32_t smem_u32(const void* p) {
    uint32_t a;
    asm("{ .reg .u64 t; cvta.to.shared.u64 t, %1; cvt.u32.u64 %0, t; }" : "=r"(a) : "l"(p));
    return a;
}

#define LDMX4(r, a) \
    asm volatile("ldmatrix.sync.aligned.m8n8.x4.shared.b16 {%0,%1,%2,%3}, [%4];" \
        : "=r"((r)[0]), "=r"((r)[1]), "=r"((r)[2]), "=r"((r)[3]) : "r"(a))

#define MMA16816(c, a, b0, b1) \
    asm volatile("mma.sync.aligned.m16n8k16.row.col.f32.bf16.bf16.f32 " \
        "{%0,%1,%2,%3}, {%4,%5,%6,%7}, {%8,%9}, {%0,%1,%2,%3};" \
        : "+f"((c)[0]), "+f"((c)[1]), "+f"((c)[2]), "+f"((c)[3]) \
        : "r"((a)[0]), "r"((a)[1]), "r"((a)[2]), "r"((a)[3]), "r"(b0), "r"(b1))

// ---------------------------------------------------------------------------
// FP32-only accurate sin/cos for |theta| <= ~4.1e4 (3-term Cody-Waite).
// ---------------------------------------------------------------------------
__device__ __forceinline__ void sincos_cw(float theta, float& S, float& C)
{
    const float INV2PI = 0.15915494309189535f;
    const float T1 = 6.28125f;
    const float T2 = 1.93500518798828125e-3f;
    const float T3 = 3.01991598e-7f;
    const float TWO_OVER_PI = 0.6366197723675814f;
    const float PIO2_HI = 1.57079637050628662109375f;
    const float PIO2_LO = -4.37113900018624283e-8f;

    float q = rintf(theta * INV2PI);
    float r = fmaf(-q, T1, theta);
    r = fmaf(-q, T2, r);
    r = fmaf(-q, T3, r);

    float qf = rintf(r * TWO_OVER_PI);
    float rr = fmaf(-qf, PIO2_HI, r);
    rr = fmaf(-qf, PIO2_LO, rr);
    int qi = (int)qf & 3;

    float x2 = rr * rr;
    float s = fmaf(x2, 2.75573192e-6f, -1.98412698e-4f);
    s = fmaf(x2, s, 8.33333333e-3f);
    s = fmaf(x2, s, -1.66666667e-1f);
    s = rr * fmaf(x2, s, 1.0f);
    float c = fmaf(x2, 2.48015873e-5f, -1.38888889e-3f);
    c = fmaf(x2, c, 4.16666667e-2f);
    c = fmaf(x2, c, -0.5f);
    c = fmaf(x2, c, 1.0f);

    switch (qi) {
        case 0: S = s;  C = c;  break;
        case 1: S = c;  C = -s; break;
        case 2: S = -s; C = -c; break;
        default: S = -c; C = s; break;
    }
}

__device__ __forceinline__ uint32_t bf16_split_pack(float v)   // (hi | lo<<16)
{
    __nv_bfloat16 hi = __float2bfloat16(v);
    float hif = __bfloat162float(hi);
    __nv_bfloat16 lo = __float2bfloat16(v - hif);
    return (uint32_t)__bfloat16_as_ushort(hi) |
           ((uint32_t)__bfloat16_as_ushort(lo) << 16);
}

// ---------------------------------------------------------------------------
// One CTA per head. kgen (fp32) -> bf16 hi/lo split of k and x -> per
// 16-lag diagonal dd: build ONE shared 16x16 Toeplitz tile, ldmatrix it,
// 3-pass split mma.sync against 16 resident accumulator tiles per warp.
// y = relu(conv) written directly from mma accumulators.
// ---------------------------------------------------------------------------
__global__ void __launch_bounds__(THREADS, 1)
s4d_mma_kernel(const float* __restrict__ x, float* __restrict__ y,
               const float* __restrict__ A_real, const float* __restrict__ A_imag,
               const float* __restrict__ Bm, const float* __restrict__ Cm,
               const float* __restrict__ inv_dt)
{
    extern __shared__ char smem_raw[];
    __shared__ float4 sp[N_STATE];
    __shared__ float sdt;

    const int h = blockIdx.x;
    const int tid = threadIdx.x;
    const int wid = tid >> 5;
    const int lane = tid & 31;

    uint32_t sbase = (smem_u32(smem_raw) + 127u) & ~127u;
    char* sm = smem_raw + (sbase - smem_u32(smem_raw));
    uint32_t* karr = (uint32_t*)(sm + OFF_KARR);

    if (tid == 0) sdt = (float)exp((double)inv_dt[h]);
    if (tid < KPAD) karr[tid] = 0;           // negative-lag zero pad
    __syncthreads();

    // ---- poles (threads 0..63), proven fp32 path ----
    if (tid < N_STATE) {
        int idx = h * N_STATE + tid;
        float Ar = -expf(A_real[idx]);
        float Ai = -A_imag[idx];
        float dt = sdt;
        float dtAr = dt * Ar;
        float dtAi = dt * Ai;
        float er = expf(dtAr);
        float S, C;
        sincos_cw(dtAi, S, C);
        float Er = fmaf(er, C, -1.0f);
        float Ei = er * S;
        float br = Bm[2 * idx], bi = Bm[2 * idx + 1];
        float cr = Cm[2 * idx], ci = Cm[2 * idx + 1];
        float bcr = br * cr - bi * ci;
        float bci = br * ci + bi * cr;
        float tr = bcr * Er - bci * Ei;
        float ti = bcr * Ei + bci * Er;
        float inv = 1.0f / (Ar * Ar + Ai * Ai);
        sp[tid] = make_float4((tr * Ar + ti * Ai) * inv, (ti * Ar - tr * Ai) * inv,
                              dtAr, dtAi);
    }
    __syncthreads();

    // truncation: decay rate dt*exp(A_real); cut at e^-9 (validated in R6)
    float rate = sdt * expf(A_real[h * N_STATE]);
    int lcut = (int)(9.0f / rate) + 1;
    if (lcut > L) lcut = L;
    int dd_end = (lcut + 15) >> 4;
    if (dd_end > 127) dd_end = 127;

    // ---- kgen: k[l] fp32 -> packed (khi | klo<<16) ----
    #pragma unroll 1
    for (int li = 0; li < L / THREADS; li++) {
        int l = tid + THREADS * li;
        float fl = (float)l;
        float acc = 0.0f;
        #pragma unroll 4
        for (int n = 0; n < N_STATE; n++) {
            float4 p = sp[n];
            float theta = p.w * fl;             // fp32 product — matches reference
            float decay = expf(p.z * fl);
            float S, C;
            sincos_cw(theta, S, C);
            acc = fmaf(decay, fmaf(p.x, C, -p.y * S), acc);
        }
        karr[KPAD + l] = bf16_split_pack(2.0f * acc);
    }

    // ---- x -> hi/lo planes: Xp[jh][b] u32 = (x[2jh], x[2jh+1]) bf16 ----
    #pragma unroll 1
    for (int idx = tid; idx < (BATCH * L) / 4; idx += THREADS) {
        int b = idx >> 9;
        int l0 = (idx & 511) * 4;
        float4 v = *(const float4*)(x + ((size_t)b * H + h) * L + l0);
        uint32_t p0 = bf16_split_pack(v.x), p1 = bf16_split_pack(v.y);
        uint32_t p2 = bf16_split_pack(v.z), p3 = bf16_split_pack(v.w);
        uint32_t w0 = ((l0 >> 1) * 8 + b) * 4;          // byte offset of word jh
        uint32_t w1 = w0 + 32;                           // jh+1 (8 words later)
        *(uint32_t*)(sm + OFF_XHI + w0) = (p0 & 0xffffu) | (p1 << 16);
        *(uint32_t*)(sm + OFF_XHI + w1) = (p2 & 0xffffu) | (p3 << 16);
        *(uint32_t*)(sm + OFF_XLO + w0) = (p0 >> 16) | (p1 & 0xffff0000u);
        *(uint32_t*)(sm + OFF_XLO + w1) = (p2 >> 16) | (p3 & 0xffff0000u);
    }

    // ---- accumulators: 16 m16n8 tiles per warp (mt = wid + 8*i) ----
    float c[16][4];
    #pragma unroll
    for (int i = 0; i < 16; i++) {
        c[i][0] = 0.0f; c[i][1] = 0.0f; c[i][2] = 0.0f; c[i][3] = 0.0f;
    }

    uint32_t arow = sbase + OFF_AHI + (uint32_t)(lane & 15) * 32u
                  + (uint32_t)(lane >> 4) * 16u;
    uint32_t xoff = (uint32_t)((lane & 3) * 8 + (lane >> 2)) * 4u;

    // ---- diagonal loop ----
    for (int dd = 0; dd <= dd_end; dd++) {
        __syncthreads();
        // build 16x16 Toeplitz tile: A[i][j] = k[16dd + i - j] (hi and lo planes)
        {
            int plane = tid >> 7;
            int q = tid & 127;
            int i = q >> 3, jw = q & 7;
            int base = KPAD + 16 * dd + i - 2 * jw;
            uint32_t v0 = karr[base];
            uint32_t v1 = karr[base - 1];
            uint32_t val = plane ? __byte_perm(v0, v1, 0x7632)
                                 : __byte_perm(v0, v1, 0x5410);
            *(uint32_t*)(sm + OFF_AHI + plane * 512 + i * 32 + jw * 4) = val;
        }
        __syncthreads();

        uint32_t ahi[4], alo[4];
        LDMX4(ahi, arow);
        LDMX4(alo, arow + 512);

        #pragma unroll
        for (int i = 0; i < 16; i++) {
            int mt = wid + 8 * i;
            if (mt >= dd) {
                uint32_t jb = (uint32_t)(mt - dd) * 256u + xoff;
                uint32_t bh0 = *(const uint32_t*)(sm + OFF_XHI + jb);
                uint32_t bh1 = *(const uint32_t*)(sm + OFF_XHI + jb + 128);
                uint32_t bl0 = *(const uint32_t*)(sm + OFF_XLO + jb);
                uint32_t bl1 = *(const uint32_t*)(sm + OFF_XLO + jb + 128);
                MMA16816(c[i], ahi, bh0, bh1);
                MMA16816(c[i], ahi, bl0, bl1);
                MMA16816(c[i], alo, bh0, bh1);
            }
        }
    }

    // ---- epilogue: ReLU + scatter stores ----
    int g = lane >> 2;
    int bcol = 2 * (lane & 3);
    #pragma unroll
    for (int i = 0; i < 16; i++) {
        int mt = wid + 8 * i;
        int t = 16 * mt + g;
        float v0 = c[i][0] > 0.0f ? c[i][0] : 0.0f;
        float v1 = c[i][1] > 0.0f ? c[i][1] : 0.0f;
        float v2 = c[i][2] > 0.0f ? c[i][2] : 0.0f;
        float v3 = c[i][3] > 0.0f ? c[i][3] : 0.0f;
        y[((size_t)bcol * H + h) * L + t]           = v0;
        y[((size_t)(bcol + 1) * H + h) * L + t]     = v1;
        y[((size_t)bcol * H + h) * L + t + 8]       = v2;
        y[((size_t)(bcol + 1) * H + h) * L + t + 8] = v3;
    }
}

// ---------------------------------------------------------------------------
extern "C" void kernel_launch(void* const* d_in, const int* in_sizes, int n_in,
                              void* d_out, int out_size)
{
    const float* x      = (const float*)d_in[0];   // (B, H, L)
    const float* A_real = (const float*)d_in[1];   // (H, N)
    const float* A_imag = (const float*)d_in[2];   // (H, N)
    const float* Bm     = (const float*)d_in[3];   // (1, H, N, 2)
    const float* Cm     = (const float*)d_in[4];   // (1, H, N, 2)
    const float* inv_dt = (const float*)d_in[5];   // (H, 1)
    float* y = (float*)d_out;                      // (B, 1, H, L)

    cudaFuncSetAttribute(s4d_mma_kernel,
                         cudaFuncAttributeMaxDynamicSharedMemorySize, SMEM_DYN);
    s4d_mma_kernel<<<H, THREADS, SMEM_DYN>>>(x, y, A_real, A_imag, Bm, Cm, inv_dt);
}

// round 9
// speedup vs baseline: 3.0687x; 1.2643x over previous
#include <cuda_runtime.h>
#include <cuda_bf16.h>
#include <math.h>
#include <stdint.h>

#define H 256
#define N_STATE 64
#define L 2048
#define BATCH 8
#define THREADS 256
#define KPAD 16

// ---- dynamic smem layout (byte offsets from 128-aligned base) ----
#define OFF_XHI   0              // u32[1024*8]: (xhi[2j],xhi[2j+1]) per batch col
#define OFF_XLO   32768
#define OFF_KARR  65536          // u32[2064]: (khi | klo<<16), [0,16) zero pad
#define SMEM_DYN  73856

__device__ __forceinline__ uint32_t smem_u32(const void* p) {
    uint32_t a;
    asm("{ .reg .u64 t; cvta.to.shared.u64 t, %1; cvt.u32.u64 %0, t; }" : "=r"(a) : "l"(p));
    return a;
}

#define MMA16816(c, a, b0, b1) \
    asm volatile("mma.sync.aligned.m16n8k16.row.col.f32.bf16.bf16.f32 " \
        "{%0,%1,%2,%3}, {%4,%5,%6,%7}, {%8,%9}, {%0,%1,%2,%3};" \
        : "+f"((c)[0]), "+f"((c)[1]), "+f"((c)[2]), "+f"((c)[3]) \
        : "r"((a)[0]), "r"((a)[1]), "r"((a)[2]), "r"((a)[3]), "r"(b0), "r"(b1))

// ---------------------------------------------------------------------------
// FP32-only accurate sin/cos for |theta| <= ~4.1e4 (3-term Cody-Waite).
// ---------------------------------------------------------------------------
__device__ __forceinline__ void sincos_cw(float theta, float& S, float& C)
{
    const float INV2PI = 0.15915494309189535f;
    const float T1 = 6.28125f;
    const float T2 = 1.93500518798828125e-3f;
    const float T3 = 3.01991598e-7f;
    const float TWO_OVER_PI = 0.6366197723675814f;
    const float PIO2_HI = 1.57079637050628662109375f;
    const float PIO2_LO = -4.37113900018624283e-8f;

    float q = rintf(theta * INV2PI);
    float r = fmaf(-q, T1, theta);
    r = fmaf(-q, T2, r);
    r = fmaf(-q, T3, r);

    float qf = rintf(r * TWO_OVER_PI);
    float rr = fmaf(-qf, PIO2_HI, r);
    rr = fmaf(-qf, PIO2_LO, rr);
    int qi = (int)qf & 3;

    float x2 = rr * rr;
    float s = fmaf(x2, 2.75573192e-6f, -1.98412698e-4f);
    s = fmaf(x2, s, 8.33333333e-3f);
    s = fmaf(x2, s, -1.66666667e-1f);
    s = rr * fmaf(x2, s, 1.0f);
    float c = fmaf(x2, 2.48015873e-5f, -1.38888889e-3f);
    c = fmaf(x2, c, 4.16666667e-2f);
    c = fmaf(x2, c, -0.5f);
    c = fmaf(x2, c, 1.0f);

    switch (qi) {
        case 0: S = s;  C = c;  break;
        case 1: S = c;  C = -s; break;
        case 2: S = -s; C = -c; break;
        default: S = -c; C = s; break;
    }
}

__device__ __forceinline__ uint32_t bf16_split_pack(float v)   // (hi | lo<<16)
{
    __nv_bfloat16 hi = __float2bfloat16(v);
    float hif = __bfloat162float(hi);
    __nv_bfloat16 lo = __float2bfloat16(v - hif);
    return (uint32_t)__bfloat16_as_ushort(hi) |
           ((uint32_t)__bfloat16_as_ushort(lo) << 16);
}

// ---------------------------------------------------------------------------
// One CTA per head. kgen (fp32) -> bf16 hi/lo split of k and x -> SYNC-FREE
// main loop: per 16-lag diagonal dd, each warp builds its Toeplitz A-fragment
// DIRECTLY from karr (6 LDS + 6 PRMT; lane (g,t) needs lags D+g-2t+{0,8,-8},
// R3==R0) and streams mma.sync against its 16 resident output tiles.
// Precision-adaptive: hi/lo correction passes only while k is large
// (16*dd*rate < 3); single-pass beyond.
// ---------------------------------------------------------------------------
__global__ void __launch_bounds__(THREADS, 2)
s4d_mma_kernel(const float* __restrict__ x, float* __restrict__ y,
               const float* __restrict__ A_real, const float* __restrict__ A_imag,
               const float* __restrict__ Bm, const float* __restrict__ Cm,
               const float* __restrict__ inv_dt)
{
    extern __shared__ char smem_raw[];
    __shared__ float4 sp[N_STATE];
    __shared__ float sdt;

    const int h = blockIdx.x;
    const int tid = threadIdx.x;
    const int wid = tid >> 5;
    const int lane = tid & 31;

    uint32_t sbase = (smem_u32(smem_raw) + 127u) & ~127u;
    char* sm = smem_raw + (sbase - smem_u32(smem_raw));
    uint32_t* karr = (uint32_t*)(sm + OFF_KARR);

    if (tid == 0) sdt = (float)exp((double)inv_dt[h]);
    if (tid < KPAD) karr[tid] = 0;           // negative-lag zero pad
    __syncthreads();

    // ---- poles (threads 0..63), proven fp32 path ----
    if (tid < N_STATE) {
        int idx = h * N_STATE + tid;
        float Ar = -expf(A_real[idx]);
        float Ai = -A_imag[idx];
        float dt = sdt;
        float dtAr = dt * Ar;
        float dtAi = dt * Ai;
        float er = expf(dtAr);
        float S, C;
        sincos_cw(dtAi, S, C);
        float Er = fmaf(er, C, -1.0f);
        float Ei = er * S;
        float br = Bm[2 * idx], bi = Bm[2 * idx + 1];
        float cr = Cm[2 * idx], ci = Cm[2 * idx + 1];
        float bcr = br * cr - bi * ci;
        float bci = br * ci + bi * cr;
        float tr = bcr * Er - bci * Ei;
        float ti = bcr * Ei + bci * Er;
        float inv = 1.0f / (Ar * Ar + Ai * Ai);
        sp[tid] = make_float4((tr * Ar + ti * Ai) * inv, (ti * Ar - tr * Ai) * inv,
                              dtAr, dtAi);
    }
    __syncthreads();

    // truncation: decay rate dt*exp(A_real); cut at e^-9 (validated)
    float rate = sdt * expf(A_real[h * N_STATE]);
    int lcut = (int)(9.0f / rate) + 1;
    if (lcut > L) lcut = L;
    int dd_end = (lcut + 15) >> 4;
    if (dd_end > 127) dd_end = 127;
    // diagonals with 16*dd*rate < 3 get the 2 lo-correction passes
    int dd3 = (int)(3.0f / (16.0f * rate)) + 1;

    // ---- kgen: k[l] fp32 -> packed (khi | klo<<16) ----
    #pragma unroll 1
    for (int li = 0; li < L / THREADS; li++) {
        int l = tid + THREADS * li;
        float fl = (float)l;
        float acc = 0.0f;
        #pragma unroll 4
        for (int n = 0; n < N_STATE; n++) {
            float4 p = sp[n];
            float theta = p.w * fl;             // fp32 product — matches reference
            float decay = expf(p.z * fl);
            float S, C;
            sincos_cw(theta, S, C);
            acc = fmaf(decay, fmaf(p.x, C, -p.y * S), acc);
        }
        karr[KPAD + l] = bf16_split_pack(2.0f * acc);
    }

    // ---- x -> hi/lo planes: word (jh,b) = (x[2jh], x[2jh+1]) bf16 ----
    #pragma unroll 1
    for (int idx = tid; idx < (BATCH * L) / 4; idx += THREADS) {
        int b = idx >> 9;
        int l0 = (idx & 511) * 4;
        float4 v = *(const float4*)(x + ((size_t)b * H + h) * L + l0);
        uint32_t p0 = bf16_split_pack(v.x), p1 = bf16_split_pack(v.y);
        uint32_t p2 = bf16_split_pack(v.z), p3 = bf16_split_pack(v.w);
        uint32_t w0 = ((l0 >> 1) * 8 + b) * 4;
        uint32_t w1 = w0 + 32;
        *(uint32_t*)(sm + OFF_XHI + w0) = (p0 & 0xffffu) | (p1 << 16);
        *(uint32_t*)(sm + OFF_XHI + w1) = (p2 & 0xffffu) | (p3 << 16);
        *(uint32_t*)(sm + OFF_XLO + w0) = (p0 >> 16) | (p1 & 0xffff0000u);
        *(uint32_t*)(sm + OFF_XLO + w1) = (p2 >> 16) | (p3 & 0xffff0000u);
    }
    __syncthreads();        // the ONLY barrier before the epilogue

    // ---- accumulators: 16 m16n8 tiles per warp (mt = wid + 8*i) ----
    float c[16][4];
    #pragma unroll
    for (int i = 0; i < 16; i++) {
        c[i][0] = 0.0f; c[i][1] = 0.0f; c[i][2] = 0.0f; c[i][3] = 0.0f;
    }

    const int g = lane >> 2;            // row group / batch col
    const int t = lane & 3;
    uint32_t xoff = (uint32_t)(t * 8 + g) * 4u;
    int ebase = KPAD + g - 2 * t;       // + 16*dd per diagonal

    // ---- sync-free diagonal loop ----
    #pragma unroll 1
    for (int dd = 0; dd <= dd_end; dd++) {
        int e = ebase + 16 * dd;
        // A-fragment directly from karr: pairs at e, e+8, e-8 (R3 == R0)
        uint32_t p0a = karr[e],     p0b = karr[e - 1];
        uint32_t p1a = karr[e + 8], p1b = karr[e + 7];
        uint32_t p2a = karr[e - 8], p2b = karr[e - 9];
        uint32_t ahi[4], alo[4];
        ahi[0] = __byte_perm(p0a, p0b, 0x5410); alo[0] = __byte_perm(p0a, p0b, 0x7632);
        ahi[1] = __byte_perm(p1a, p1b, 0x5410); alo[1] = __byte_perm(p1a, p1b, 0x7632);
        ahi[2] = __byte_perm(p2a, p2b, 0x5410); alo[2] = __byte_perm(p2a, p2b, 0x7632);
        ahi[3] = ahi[0];                         alo[3] = alo[0];

        bool three = dd < dd3;
        #pragma unroll
        for (int i = 0; i < 16; i++) {
            int mt = wid + 8 * i;
            if (mt >= dd) {
                uint32_t jb = (uint32_t)(mt - dd) * 256u + xoff;
                uint32_t bh0 = *(const uint32_t*)(sm + OFF_XHI + jb);
                uint32_t bh1 = *(const uint32_t*)(sm + OFF_XHI + jb + 128);
                MMA16816(c[i], ahi, bh0, bh1);
                if (three) {
                    uint32_t bl0 = *(const uint32_t*)(sm + OFF_XLO + jb);
                    uint32_t bl1 = *(const uint32_t*)(sm + OFF_XLO + jb + 128);
                    MMA16816(c[i], ahi, bl0, bl1);
                    MMA16816(c[i], alo, bh0, bh1);
                }
            }
        }
    }

    // ---- epilogue: ReLU + scatter stores ----
    int bcol = 2 * t;
    #pragma unroll
    for (int i = 0; i < 16; i++) {
        int mt = wid + 8 * i;
        int tt = 16 * mt + g;
        float v0 = c[i][0] > 0.0f ? c[i][0] : 0.0f;
        float v1 = c[i][1] > 0.0f ? c[i][1] : 0.0f;
        float v2 = c[i][2] > 0.0f ? c[i][2] : 0.0f;
        float v3 = c[i][3] > 0.0f ? c[i][3] : 0.0f;
        y[((size_t)bcol * H + h) * L + tt]           = v0;
        y[((size_t)(bcol + 1) * H + h) * L + tt]     = v1;
        y[((size_t)bcol * H + h) * L + tt + 8]       = v2;
        y[((size_t)(bcol + 1) * H + h) * L + tt + 8] = v3;
    }
}

// ---------------------------------------------------------------------------
extern "C" void kernel_launch(void* const* d_in, const int* in_sizes, int n_in,
                              void* d_out, int out_size)
{
    const float* x      = (const float*)d_in[0];   // (B, H, L)
    const float* A_real = (const float*)d_in[1];   // (H, N)
    const float* A_imag = (const float*)d_in[2];   // (H, N)
    const float* Bm     = (const float*)d_in[3];   // (1, H, N, 2)
    const float* Cm     = (const float*)d_in[4];   // (1, H, N, 2)
    const float* inv_dt = (const float*)d_in[5];   // (H, 1)
    float* y = (float*)d_out;                      // (B, 1, H, L)

    cudaFuncSetAttribute(s4d_mma_kernel,
                         cudaFuncAttributeMaxDynamicSharedMemorySize, SMEM_DYN);
    s4d_mma_kernel<<<H, THREADS, SMEM_DYN>>>(x, y, A_real, A_imag, Bm, Cm, inv_dt);
}

// round 10
// speedup vs baseline: 4.7110x; 1.5352x over previous
#include <cuda_runtime.h>
#include <cuda_bf16.h>
#include <math.h>
#include <stdint.h>

#define H 256
#define N_STATE 64
#define L 2048
#define BATCH 8
#define THREADS 256
#define KPAD 16

// ---- dynamic smem layout (byte offsets from 128-aligned base) ----
// X planes: per 16-lag tile, 64 u32 words; word (jh,b) at
// tile*256B + (((jh&3)*8 + b)*2 + (jh>>2))*4  -> fragment pairs adjacent (LDS.64)
#define OFF_XHI   0
#define OFF_XLO   32768
#define OFF_KARR  65536          // u32[2064]: (khi | klo<<16), [0,16) zero pad
#define SMEM_DYN  73856

__device__ __forceinline__ uint32_t smem_u32(const void* p) {
    uint32_t a;
    asm("{ .reg .u64 t; cvta.to.shared.u64 t, %1; cvt.u32.u64 %0, t; }" : "=r"(a) : "l"(p));
    return a;
}

#define MMA16816(c, a, b0, b1) \
    asm volatile("mma.sync.aligned.m16n8k16.row.col.f32.bf16.bf16.f32 " \
        "{%0,%1,%2,%3}, {%4,%5,%6,%7}, {%8,%9}, {%0,%1,%2,%3};" \
        : "+f"((c)[0]), "+f"((c)[1]), "+f"((c)[2]), "+f"((c)[3]) \
        : "r"((a)[0]), "r"((a)[1]), "r"((a)[2]), "r"((a)[3]), "r"(b0), "r"(b1))

// ---------------------------------------------------------------------------
// FP32-only accurate sin/cos for |theta| <= ~4.1e4 (3-term Cody-Waite).
// ---------------------------------------------------------------------------
__device__ __forceinline__ void sincos_cw(float theta, float& S, float& C)
{
    const float INV2PI = 0.15915494309189535f;
    const float T1 = 6.28125f;
    const float T2 = 1.93500518798828125e-3f;
    const float T3 = 3.01991598e-7f;
    const float TWO_OVER_PI = 0.6366197723675814f;
    const float PIO2_HI = 1.57079637050628662109375f;
    const float PIO2_LO = -4.37113900018624283e-8f;

    float q = rintf(theta * INV2PI);
    float r = fmaf(-q, T1, theta);
    r = fmaf(-q, T2, r);
    r = fmaf(-q, T3, r);

    float qf = rintf(r * TWO_OVER_PI);
    float rr = fmaf(-qf, PIO2_HI, r);
    rr = fmaf(-qf, PIO2_LO, rr);
    int qi = (int)qf & 3;

    float x2 = rr * rr;
    float s = fmaf(x2, 2.75573192e-6f, -1.98412698e-4f);
    s = fmaf(x2, s, 8.33333333e-3f);
    s = fmaf(x2, s, -1.66666667e-1f);
    s = rr * fmaf(x2, s, 1.0f);
    float c = fmaf(x2, 2.48015873e-5f, -1.38888889e-3f);
    c = fmaf(x2, c, 4.16666667e-2f);
    c = fmaf(x2, c, -0.5f);
    c = fmaf(x2, c, 1.0f);

    switch (qi) {
        case 0: S = s;  C = c;  break;
        case 1: S = c;  C = -s; break;
        case 2: S = -s; C = -c; break;
        default: S = -c; C = s; break;
    }
}

__device__ __forceinline__ uint32_t bf16_split_pack(float v)   // (hi | lo<<16)
{
    __nv_bfloat16 hi = __float2bfloat16(v);
    float hif = __bfloat162float(hi);
    __nv_bfloat16 lo = __float2bfloat16(v - hif);
    return (uint32_t)__bfloat16_as_ushort(hi) |
           ((uint32_t)__bfloat16_as_ushort(lo) << 16);
}

// ---------------------------------------------------------------------------
// One CTA per head. kgen via POLE-POWER RECURRENCE (z^tid once per pole, then
// v *= z^256 per 256-stride step: ~12 ops/(n,l) vs ~50) -> bf16 hi/lo planes
// -> sync-free diagonal mma.sync loop (A-fragment straight from karr).
// ---------------------------------------------------------------------------
__global__ void __launch_bounds__(THREADS, 2)
s4d_mma_kernel(const float* __restrict__ x, float* __restrict__ y,
               const float* __restrict__ A_real, const float* __restrict__ A_imag,
               const float* __restrict__ Bm, const float* __restrict__ Cm,
               const float* __restrict__ inv_dt)
{
    extern __shared__ char smem_raw[];
    __shared__ float4 sp[N_STATE];    // {Ceff_r, Ceff_i, dtA_r, dtA_i}
    __shared__ float2 spz[N_STATE];   // z^256 = exp(256*dtA)
    __shared__ float sdt;

    const int h = blockIdx.x;
    const int tid = threadIdx.x;
    const int wid = tid >> 5;
    const int lane = tid & 31;

    uint32_t sbase = (smem_u32(smem_raw) + 127u) & ~127u;
    char* sm = smem_raw + (sbase - smem_u32(smem_raw));
    uint32_t* karr = (uint32_t*)(sm + OFF_KARR);

    if (tid == 0) sdt = (float)exp((double)inv_dt[h]);
    if (tid < KPAD) karr[tid] = 0;           // negative-lag zero pad
    __syncthreads();

    // ---- poles (threads 0..63) ----
    if (tid < N_STATE) {
        int idx = h * N_STATE + tid;
        float Ar = -expf(A_real[idx]);
        float Ai = -A_imag[idx];
        float dt = sdt;
        float dtAr = dt * Ar;
        float dtAi = dt * Ai;
        float er = expf(dtAr);
        float S, C;
        sincos_cw(dtAi, S, C);
        float Er = fmaf(er, C, -1.0f);
        float Ei = er * S;
        float br = Bm[2 * idx], bi = Bm[2 * idx + 1];
        float cr = Cm[2 * idx], ci = Cm[2 * idx + 1];
        float bcr = br * cr - bi * ci;
        float bci = br * ci + bi * cr;
        float tr = bcr * Er - bci * Ei;
        float ti = bcr * Ei + bci * Er;
        float inv = 1.0f / (Ar * Ar + Ai * Ai);
        sp[tid] = make_float4((tr * Ar + ti * Ai) * inv, (ti * Ar - tr * Ai) * inv,
                              dtAr, dtAi);
        // z^256
        float d256 = expf(dtAr * 256.0f);
        float S2, C2;
        sincos_cw(dtAi * 256.0f, S2, C2);
        spz[tid] = make_float2(d256 * C2, d256 * S2);
    }
    __syncthreads();

    // truncation: decay rate dt*exp(A_real); cut at e^-9 (validated)
    float rate = sdt * expf(A_real[h * N_STATE]);
    int lcut = (int)(9.0f / rate) + 1;
    if (lcut > L) lcut = L;
    int dd_end = (lcut + 15) >> 4;
    if (dd_end > 127) dd_end = 127;
    int dd3 = (int)(3.0f / (16.0f * rate)) + 1;   // 3-pass region

    // ---- kgen via recurrence: thread owns l = tid + 256*i, i = 0..7 ----
    {
        float kacc[8];
        #pragma unroll
        for (int i = 0; i < 8; i++) kacc[i] = 0.0f;
        float ftid = (float)tid;

        #pragma unroll 1
        for (int n = 0; n < N_STATE; n++) {
            float4 p = sp[n];
            float2 z = spz[n];
            // v = z^tid (fp32 product phase — matches reference at l=tid)
            float theta = p.w * ftid;
            float decay = expf(p.z * ftid);
            float S, C;
            sincos_cw(theta, S, C);
            float vr = decay * C;
            float vi = decay * S;
            #pragma unroll
            for (int i = 0; i < 8; i++) {
                kacc[i] = fmaf(p.x, vr, kacc[i]);
                kacc[i] = fmaf(-p.y, vi, kacc[i]);
                float nvr = vr * z.x - vi * z.y;
                float nvi = vr * z.y + vi * z.x;
                vr = nvr; vi = nvi;
            }
        }
        #pragma unroll
        for (int i = 0; i < 8; i++)
            karr[KPAD + tid + 256 * i] = bf16_split_pack(2.0f * kacc[i]);
    }

    // ---- x -> hi/lo planes, paired layout for LDS.64 fragments ----
    #pragma unroll 1
    for (int idx = tid; idx < (BATCH * L) / 4; idx += THREADS) {
        int b = idx >> 9;
        int l0 = (idx & 511) * 4;
        float4 v = *(const float4*)(x + ((size_t)b * H + h) * L + l0);
        uint32_t p0 = bf16_split_pack(v.x), p1 = bf16_split_pack(v.y);
        uint32_t p2 = bf16_split_pack(v.z), p3 = bf16_split_pack(v.w);
        int jh0 = l0 >> 1;                 // first jh (covers l0, l0+1)
        #pragma unroll
        for (int e = 0; e < 2; e++) {
            int jh = jh0 + e;
            uint32_t whi = e ? ((p2 & 0xffffu) | (p3 << 16))
                             : ((p0 & 0xffffu) | (p1 << 16));
            uint32_t wlo = e ? ((p2 >> 16) | (p3 & 0xffff0000u))
                             : ((p0 >> 16) | (p1 & 0xffff0000u));
            int lj = jh & 7;
            uint32_t woff = ((uint32_t)(jh >> 3) * 64u
                           + ((uint32_t)(lj & 3) * 8u + (uint32_t)b) * 2u
                           + (uint32_t)(lj >> 2)) * 4u;
            *(uint32_t*)(sm + OFF_XHI + woff) = whi;
            *(uint32_t*)(sm + OFF_XLO + woff) = wlo;
        }
    }
    __syncthreads();        // the ONLY barrier before the epilogue

    // ---- accumulators: 16 m16n8 tiles per warp (mt = wid + 8*i) ----
    float c[16][4];
    #pragma unroll
    for (int i = 0; i < 16; i++) {
        c[i][0] = 0.0f; c[i][1] = 0.0f; c[i][2] = 0.0f; c[i][3] = 0.0f;
    }

    const int g = lane >> 2;            // row group / batch col
    const int t = lane & 3;
    uint32_t xoff = (uint32_t)(t * 8 + g) * 8u;    // byte offset of LDS.64 pair
    int ebase = KPAD + g - 2 * t;       // + 16*dd per diagonal

    // ---- sync-free diagonal loop ----
    #pragma unroll 1
    for (int dd = 0; dd <= dd_end; dd++) {
        int e = ebase + 16 * dd;
        uint32_t p0a = karr[e],     p0b = karr[e - 1];
        uint32_t p1a = karr[e + 8], p1b = karr[e + 7];
        uint32_t p2a = karr[e - 8], p2b = karr[e - 9];
        uint32_t ahi[4], alo[4];
        ahi[0] = __byte_perm(p0a, p0b, 0x5410); alo[0] = __byte_perm(p0a, p0b, 0x7632);
        ahi[1] = __byte_perm(p1a, p1b, 0x5410); alo[1] = __byte_perm(p1a, p1b, 0x7632);
        ahi[2] = __byte_perm(p2a, p2b, 0x5410); alo[2] = __byte_perm(p2a, p2b, 0x7632);
        ahi[3] = ahi[0];                         alo[3] = alo[0];

        bool three = dd < dd3;
        #pragma unroll
        for (int i = 0; i < 16; i++) {
            int mt = wid + 8 * i;
            if (mt >= dd) {
                uint32_t jb = (uint32_t)(mt - dd) * 256u + xoff;
                uint2 bh = *(const uint2*)(sm + OFF_XHI + jb);
                MMA16816(c[i], ahi, bh.x, bh.y);
                if (three) {
                    uint2 bl = *(const uint2*)(sm + OFF_XLO + jb);
                    MMA16816(c[i], ahi, bl.x, bl.y);
                    MMA16816(c[i], alo, bh.x, bh.y);
                }
            }
        }
    }

    // ---- epilogue: ReLU + scatter stores ----
    int bcol = 2 * t;
    #pragma unroll
    for (int i = 0; i < 16; i++) {
        int mt = wid + 8 * i;
        int tt = 16 * mt + g;
        float v0 = c[i][0] > 0.0f ? c[i][0] : 0.0f;
        float v1 = c[i][1] > 0.0f ? c[i][1] : 0.0f;
        float v2 = c[i][2] > 0.0f ? c[i][2] : 0.0f;
        float v3 = c[i][3] > 0.0f ? c[i][3] : 0.0f;
        y[((size_t)bcol * H + h) * L + tt]           = v0;
        y[((size_t)(bcol + 1) * H + h) * L + tt]     = v1;
        y[((size_t)bcol * H + h) * L + tt + 8]       = v2;
        y[((size_t)(bcol + 1) * H + h) * L + tt + 8] = v3;
    }
}

// ---------------------------------------------------------------------------
extern "C" void kernel_launch(void* const* d_in, const int* in_sizes, int n_in,
                              void* d_out, int out_size)
{
    const float* x      = (const float*)d_in[0];   // (B, H, L)
    const float* A_real = (const float*)d_in[1];   // (H, N)
    const float* A_imag = (const float*)d_in[2];   // (H, N)
    const float* Bm     = (const float*)d_in[3];   // (1, H, N, 2)
    const float* Cm     = (const float*)d_in[4];   // (1, H, N, 2)
    const float* inv_dt = (const float*)d_in[5];   // (H, 1)
    float* y = (float*)d_out;                      // (B, 1, H, L)

    cudaFuncSetAttribute(s4d_mma_kernel,
                         cudaFuncAttributeMaxDynamicSharedMemorySize, SMEM_DYN);
    s4d_mma_kernel<<<H, THREADS, SMEM_DYN>>>(x, y, A_real, A_imag, Bm, Cm, inv_dt);
}